// round 7
// baseline (speedup 1.0000x reference)
#include <cuda_runtime.h>
#include <cuda_bf16.h>
#include <math.h>

// RankingLoss: B=65536 rows, C=1024 classes, float32 scores, int32 labels.
// loss = mean_b [ log1p(exp(2*(2.5 - s_pos))) + log1p(exp(2*(0.5 + s_neg))) ]
// Persistent grid-stride version: grid = 148 SMs * 8 CTAs, one wave, each
// warp processes ~7 rows back-to-back (no wave-transition seams, prologue
// paid once, cross-row load/reduce overlap).

#define NUM_B 65536
#define NUM_C 1024
#define WARPS_PER_BLOCK 8
#define GRID_CTAS (148 * 8)   // one full wave at occupancy 8

__device__ double g_acc = 0.0;
__device__ unsigned int g_done = 0;

__device__ __forceinline__ float softplus_g(float t) {
    return (t > 20.0f) ? t : log1pf(__expf(t));
}

__device__ __forceinline__ void consume_f4(float4 v, int f4, int lbl,
                                           float& vmax, float& spos) {
    const int col = f4 * 4;
    float a0 = v.x, a1 = v.y, a2 = v.z, a3 = v.w;
    if (col + 0 == lbl) { spos = a0; a0 = -INFINITY; }
    if (col + 1 == lbl) { spos = a1; a1 = -INFINITY; }
    if (col + 2 == lbl) { spos = a2; a2 = -INFINITY; }
    if (col + 3 == lbl) { spos = a3; a3 = -INFINITY; }
    vmax = fmaxf(vmax, fmaxf(fmaxf(a0, a1), fmaxf(a2, a3)));
}

__global__ void __launch_bounds__(WARPS_PER_BLOCK * 32, 8)
ranking_loss_kernel(const float* __restrict__ scores,
                    const int* __restrict__ labels,
                    float* __restrict__ out)
{
    const int lane   = threadIdx.x & 31;
    const int warp   = threadIdx.x >> 5;
    const int gwarp  = blockIdx.x * WARPS_PER_BLOCK + warp;
    const int nwarps = GRID_CTAS * WARPS_PER_BLOCK;   // 9472

    float warp_loss = 0.0f;   // lane 0 accumulates across rows

    for (int row = gwarp; row < NUM_B; row += nwarps) {
        const int lbl = labels[row];
        const float4* __restrict__ rp =
            (const float4*)(scores + (size_t)row * NUM_C);

        float vmax = -INFINITY;
        float spos = -INFINITY;

        // Two batches of 4 independent LDG.128 (MLP=4, regs<=32).
        {
            float4 v0 = rp[0 * 32 + lane];
            float4 v1 = rp[1 * 32 + lane];
            float4 v2 = rp[2 * 32 + lane];
            float4 v3 = rp[3 * 32 + lane];
            consume_f4(v0, 0 * 32 + lane, lbl, vmax, spos);
            consume_f4(v1, 1 * 32 + lane, lbl, vmax, spos);
            consume_f4(v2, 2 * 32 + lane, lbl, vmax, spos);
            consume_f4(v3, 3 * 32 + lane, lbl, vmax, spos);
        }
        {
            float4 v0 = rp[4 * 32 + lane];
            float4 v1 = rp[5 * 32 + lane];
            float4 v2 = rp[6 * 32 + lane];
            float4 v3 = rp[7 * 32 + lane];
            consume_f4(v0, 4 * 32 + lane, lbl, vmax, spos);
            consume_f4(v1, 5 * 32 + lane, lbl, vmax, spos);
            consume_f4(v2, 6 * 32 + lane, lbl, vmax, spos);
            consume_f4(v3, 7 * 32 + lane, lbl, vmax, spos);
        }

        // Warp tree reduction (max for both; one lane holds spos).
        #pragma unroll
        for (int o = 16; o > 0; o >>= 1) {
            vmax = fmaxf(vmax, __shfl_xor_sync(0xffffffffu, vmax, o));
            spos = fmaxf(spos, __shfl_xor_sync(0xffffffffu, spos, o));
        }

        if (lane == 0) {
            const float s_neg = (lbl == 0) ? 0.0f : vmax;
            warp_loss += softplus_g(2.0f * (2.5f - spos))
                       + softplus_g(2.0f * (0.5f + s_neg));
        }
    }

    // Block reduction of per-warp partial sums.
    __shared__ float s_part[WARPS_PER_BLOCK];
    if (lane == 0) s_part[warp] = warp_loss;
    __syncthreads();

    if (threadIdx.x == 0) {
        float blk = 0.0f;
        #pragma unroll
        for (int i = 0; i < WARPS_PER_BLOCK; ++i) blk += s_part[i];
        atomicAdd(&g_acc, (double)blk);
        __threadfence();
        const unsigned int ticket = atomicAdd(&g_done, 1u);
        if (ticket == gridDim.x - 1) {
            *out = (float)(g_acc / (double)NUM_B);
            g_acc = 0.0;
            g_done = 0;
        }
    }
}

extern "C" void kernel_launch(void* const* d_in, const int* in_sizes, int n_in,
                              void* d_out, int out_size)
{
    const float* scores = (const float*)d_in[0];
    const int*   labels = (const int*)d_in[1];
    float*       out    = (float*)d_out;

    ranking_loss_kernel<<<GRID_CTAS, WARPS_PER_BLOCK * 32>>>(scores, labels, out);
}